// round 1
// baseline (speedup 1.0000x reference)
#include <cuda_runtime.h>
#include <math.h>

// ---------------------------------------------------------------------------
// fs_net_loss: 5-component FS-Net loss.
// Dominant cost: mean|pred_Recon - gt_Recon| over 128*32768*3 f32 (2x 50MB read).
// Kernel A: streaming float4 L1 reduction -> per-block partials (device scratch).
// Kernel B: 1 block; per-batch rot1/rot2/tran/size + final reduce + write out[5].
// ---------------------------------------------------------------------------

#define BS 128
#define N_PTS 32768
#define RECON_ELEMS (BS * N_PTS * 3)          // 12,582,912 (divisible by 4)
#define RECON_V4   (RECON_ELEMS / 4)          // 3,145,728
#define NBLK 2048
#define NTHR 256
#define BASE 12

__device__ float g_recon_partial[NBLK];

__global__ __launch_bounds__(NTHR) void recon_l1_kernel(
    const float4* __restrict__ a, const float4* __restrict__ b)
{
    float s = 0.0f;
    const int stride = gridDim.x * blockDim.x;
    for (int i = blockIdx.x * blockDim.x + threadIdx.x; i < RECON_V4; i += stride) {
        float4 x = a[i];
        float4 y = b[i];
        s += fabsf(x.x - y.x) + fabsf(x.y - y.y) +
             fabsf(x.z - y.z) + fabsf(x.w - y.w);
    }
    __shared__ float sm[NTHR];
    sm[threadIdx.x] = s;
    __syncthreads();
    #pragma unroll
    for (int off = NTHR / 2; off > 0; off >>= 1) {
        if (threadIdx.x < off) sm[threadIdx.x] += sm[threadIdx.x + off];
        __syncthreads();
    }
    if (threadIdx.x == 0) g_recon_partial[blockIdx.x] = sm[0];
}

__global__ __launch_bounds__(BS) void final_kernel(
    const float* __restrict__ pR1,   // [BS,3]
    const float* __restrict__ pR2,   // [BS,3]
    const float* __restrict__ pT,    // [BS,3]
    const float* __restrict__ pS,    // [BS,3]
    const float* __restrict__ gR,    // [BS,3,3] row-major
    const float* __restrict__ gT,    // [BS,3]
    const float* __restrict__ gS,    // [BS,3]
    const int*   __restrict__ sym,   // [BS,6] int32
    float* __restrict__ out)         // [5]
{
    const int b = threadIdx.x;       // 0..127, one batch each

    // ---- tail-reduce recon partials (deterministic tree) ----
    float rsum = 0.0f;
    #pragma unroll
    for (int i = b; i < NBLK; i += BS) rsum += g_recon_partial[i];

    // ---- per-batch small losses ----
    const float* R = gR + b * 9;
    const float r00 = R[0], r01 = R[1], r02 = R[2];
    const float r10 = R[3], r11 = R[4], r12 = R[5];
    const float r20 = R[6], r21 = R[7], r22 = R[8];

    // rot1: candidates are +/- column 1 of R (R @ [0,1,0] and R @ [0,-1,0])
    const float p0 = pR1[b * 3 + 0], p1 = pR1[b * 3 + 1], p2 = pR1[b * 3 + 2];
    const float l1a = (fabsf(p0 - r01) + fabsf(p1 - r11) + fabsf(p2 - r21)) * (1.0f / 3.0f);
    const float l1b = (fabsf(p0 + r01) + fabsf(p1 + r11) + fabsf(p2 + r21)) * (1.0f / 3.0f);
    const float rot1 = (sym[b * 6 + 2] == 1) ? fminf(l1a, l1b) : l1a;

    // rot2: candidates cos(th_k)*col0(R) - sin(th_k)*col2(R), k = 0..BASE-1
    const float q0 = pR2[b * 3 + 0], q1 = pR2[b * 3 + 1], q2 = pR2[b * 3 + 2];
    float best = 3.402823466e38f;
    #pragma unroll
    for (int k = 0; k < BASE; k++) {
        const float th = ((float)k / (float)BASE) * 6.28318530717958647692f;
        float sk, ck;
        sincosf(th, &sk, &ck);
        const float w0 = ck * r00 - sk * r02;
        const float w1 = ck * r10 - sk * r12;
        const float w2 = ck * r20 - sk * r22;
        const float l = (fabsf(q0 - w0) + fabsf(q1 - w1) + fabsf(q2 - w2)) * (1.0f / 3.0f);
        best = fminf(best, l);
    }
    const float maskf = (sym[b * 6 + 0] == 0) ? 1.0f : 0.0f;
    const float rot2m = best * maskf;

    // tran / size: per-batch |diff| sums (3 comps each)
    const float tr = fabsf(pT[b * 3 + 0] - gT[b * 3 + 0]) +
                     fabsf(pT[b * 3 + 1] - gT[b * 3 + 1]) +
                     fabsf(pT[b * 3 + 2] - gT[b * 3 + 2]);
    const float sz = fabsf(pS[b * 3 + 0] - gS[b * 3 + 0]) +
                     fabsf(pS[b * 3 + 1] - gS[b * 3 + 1]) +
                     fabsf(pS[b * 3 + 2] - gS[b * 3 + 2]);

    // ---- block reduce 6 quantities across 128 threads ----
    __shared__ float sm[6][BS];
    sm[0][b] = rot1;
    sm[1][b] = rot2m;
    sm[2][b] = maskf;
    sm[3][b] = tr;
    sm[4][b] = sz;
    sm[5][b] = rsum;
    __syncthreads();
    #pragma unroll
    for (int off = BS / 2; off > 0; off >>= 1) {
        if (b < off) {
            #pragma unroll
            for (int j = 0; j < 6; j++) sm[j][b] += sm[j][b + off];
        }
        __syncthreads();
    }

    if (b == 0) {
        const float valid = sm[2][0];
        out[0] = 8.0f * sm[0][0] * (1.0f / (float)BS);
        out[1] = 8.0f * ((valid > 0.0f) ? sm[1][0] / fmaxf(valid, 1.0f) : 0.0f);
        out[2] = 8.0f * sm[5][0] * (1.0f / (float)RECON_ELEMS);
        out[3] = 8.0f * sm[3][0] * (1.0f / (float)(BS * 3));
        out[4] = 8.0f * sm[4][0] * (1.0f / (float)(BS * 3));
    }
}

extern "C" void kernel_launch(void* const* d_in, const int* in_sizes, int n_in,
                              void* d_out, int out_size)
{
    const float* pR1  = (const float*)d_in[0];
    const float* pR2  = (const float*)d_in[1];
    const float* pRec = (const float*)d_in[2];
    const float* pT   = (const float*)d_in[3];
    const float* pS   = (const float*)d_in[4];
    const float* gR   = (const float*)d_in[5];
    const float* gRec = (const float*)d_in[6];
    const float* gT   = (const float*)d_in[7];
    const float* gS   = (const float*)d_in[8];
    const int*   sym  = (const int*)d_in[9];
    float* out = (float*)d_out;

    recon_l1_kernel<<<NBLK, NTHR>>>((const float4*)pRec, (const float4*)gRec);
    final_kernel<<<1, BS>>>(pR1, pR2, pT, pS, gR, gT, gS, sym, out);
}